// round 16
// baseline (speedup 1.0000x reference)
#include <cuda_runtime.h>
#include <math.h>
#include <stdint.h>

#define QSCALE 0.08838834764831845f   // (2*64)^-0.5
#define BSCALE 0.7071067811865476f    // 2^-0.5

// ---------------- device scratch ----------------
__device__ float g_q[4*8*512*64];      // tf32-rounded, prescaled
__device__ float g_k[4*8*512*64];      // tf32-rounded
__device__ float g_v[4*8*512*64];      // tf32-rounded
__device__ float g_bias[4*512*512];
__device__ float g_p[4*8*512*512];     // S (fp32) then P (tf32-rounded)
__device__ float g_s1[4*512*768];      // tf32-rounded [ctx | E]
__device__ float g_wcomb[512*768];     // tf32-rounded
__device__ float g_bfinal[512];
__device__ float g_M[512*256];
__device__ float g_c[512];

// ---------------- packed fp32x2 FMA ----------------
__device__ __forceinline__ void ffma2(float2& c, float2 a, float2 b) {
    unsigned long long ca = *reinterpret_cast<const unsigned long long*>(&a);
    unsigned long long cb = *reinterpret_cast<const unsigned long long*>(&b);
    unsigned long long cc = *reinterpret_cast<unsigned long long*>(&c);
    asm("fma.rn.f32x2 %0, %1, %2, %0;" : "+l"(cc) : "l"(ca), "l"(cb));
    *reinterpret_cast<unsigned long long*>(&c) = cc;
}

// ---------------- tf32 helpers ----------------
__device__ __forceinline__ unsigned f2t(float x) {
    unsigned u; asm("cvt.rna.tf32.f32 %0, %1;" : "=r"(u) : "f"(x)); return u;
}
__device__ __forceinline__ float f2tf(float x) {
    return __uint_as_float(f2t(x));
}
__device__ __forceinline__ void mma8(float4& d, unsigned a0, unsigned a1, unsigned a2, unsigned a3,
                                     unsigned b0, unsigned b1) {
    asm volatile("mma.sync.aligned.m16n8k8.row.col.f32.tf32.tf32.f32 "
                 "{%0,%1,%2,%3},{%4,%5,%6,%7},{%8,%9},{%0,%1,%2,%3};"
                 : "+f"(d.x), "+f"(d.y), "+f"(d.z), "+f"(d.w)
                 : "r"(a0), "r"(a1), "r"(a2), "r"(a3), "r"(b0), "r"(b1));
}

// ---------------- cp.async helpers ----------------
__device__ __forceinline__ void cp4(void* s, const void* g) {
    unsigned sa = (unsigned)__cvta_generic_to_shared(s);
    asm volatile("cp.async.ca.shared.global [%0], [%1], 4;" :: "r"(sa), "l"(g));
}
__device__ __forceinline__ void cp_commit() { asm volatile("cp.async.commit_group;"); }
__device__ __forceinline__ void cp_wait1()  { asm volatile("cp.async.wait_group 1;"); }
__device__ __forceinline__ void cp_wait0()  { asm volatile("cp.async.wait_group 0;"); }

// 4-plane split layout: element (row m, k) lives at plane (k&3), word m*4+(k>>2).
#define PLB 264   // 64-row plane stride (words); PLB%32==8 -> conflict-free frags

// Fragment stage for pre-rounded data: raw uint4 loads, no CVT.
__device__ __forceinline__ void gemm_stage_raw(const float* a, const float* bsm,
                                               int warp_m, int warp_n, int r, int c,
                                               float4 (&acc)[2][4]) {
    const unsigned* au = (const unsigned*)a;
    const unsigned* bu_ = (const unsigned*)bsm;
    uint4 bu[4];
    #pragma unroll
    for (int j = 0; j < 4; j++)
        bu[j] = *(const uint4*)&bu_[c*PLB + (warp_n + j*8 + r)*4];
    #pragma unroll
    for (int i = 0; i < 2; i++) {
        uint4 lo = *(const uint4*)&au[c*PLB + (warp_m + i*16 + r)*4];
        uint4 hi = *(const uint4*)&au[c*PLB + (warp_m + i*16 + r + 8)*4];
        #pragma unroll
        for (int j = 0; j < 4; j++) {
            mma8(acc[i][j], lo.x, hi.x, lo.y, hi.y, bu[j].x, bu[j].y);
            mma8(acc[i][j], lo.z, hi.z, lo.w, hi.w, bu[j].z, bu[j].w);
        }
    }
}

// ---------------- prep ----------------
__global__ void prep1_kernel(const float* __restrict__ W_Ke, const float* __restrict__ b_Ke,
                             const float* __restrict__ W_eo, const float* __restrict__ b_eo) {
    int d2 = blockIdx.x, j = threadIdx.x;
    int h = j >> 5, e = j & 31;
    const float* weo = W_eo + d2 * 256;
    float acc = 0.f;
    #pragma unroll
    for (int de = 0; de < 32; de++)
        acc = fmaf(weo[h*32 + de], W_Ke[de*32 + e], acc);
    g_M[d2*256 + j] = acc;
    if (j == 0) {
        float c = b_eo[d2];
        for (int jj = 0; jj < 256; jj++) c = fmaf(weo[jj], b_Ke[jj & 31], c);
        g_c[d2] = c;
    }
}

__global__ void prep2_kernel(const float* __restrict__ W_o, const float* __restrict__ b_o) {
    int d = blockIdx.x, j4 = threadIdx.x;   // 0..63
    const float* wo = W_o + (size_t)d * 1024;
    float4 acc = make_float4(0.f,0.f,0.f,0.f);
    float bacc = 0.f;
    #pragma unroll 4
    for (int d2 = 0; d2 < 512; d2++) {
        float wv = wo[512 + d2];
        float4 m = *(const float4*)&g_M[d2*256 + j4*4];
        acc.x = fmaf(wv, m.x, acc.x); acc.y = fmaf(wv, m.y, acc.y);
        acc.z = fmaf(wv, m.z, acc.z); acc.w = fmaf(wv, m.w, acc.w);
        if (j4 == 0) bacc = fmaf(wv, g_c[d2], bacc);
    }
    float4 o = make_float4(f2tf(acc.x), f2tf(acc.y), f2tf(acc.z), f2tf(acc.w));
    *(float4*)&g_wcomb[(size_t)d*768 + 512 + j4*4] = o;
    #pragma unroll
    for (int t = 0; t < 8; t++)
        g_wcomb[(size_t)d*768 + j4*8 + t] = f2tf(wo[j4*8 + t]);
    if (j4 == 0) g_bfinal[d] = b_o[d] + bacc;
}

// ---------------- QKV projection: tf32 MMA, 3-stage cp.async, CTA 64x64 ----
// grid (8, 32, 3): (head, m-tile, matrix). All outputs tf32-rounded.
__global__ void __launch_bounds__(128) proj_kernel(
    const float* __restrict__ Q, const float* __restrict__ K, const float* __restrict__ V,
    const float* __restrict__ WQ, const float* __restrict__ WK, const float* __restrict__ WV,
    const float* __restrict__ bQ, const float* __restrict__ bK, const float* __restrict__ bV) {
    __shared__ float As[3][4*PLB];
    __shared__ float Bs[3][4*PLB];
    int z = blockIdx.z;
    const float* A    = (z == 0) ? Q  : (z == 1) ? K  : V;
    const float* W    = (z == 0) ? WQ : (z == 1) ? WK : WV;
    const float* bias = (z == 0) ? bQ : (z == 1) ? bK : bV;
    float* dst        = (z == 0) ? g_q : (z == 1) ? g_k : g_v;
    int m0 = blockIdx.y * 64, n0 = blockIdx.x * 64;
    int tid = threadIdx.x, lane = tid & 31, w = tid >> 5;
    int warp_m = (w & 1) * 32, warp_n = (w >> 1) * 32;
    int r = lane >> 2, c = lane & 3;
    int h = blockIdx.x;

    float4 acc[2][4];
    #pragma unroll
    for (int i = 0; i < 2; i++)
        #pragma unroll
        for (int j = 0; j < 4; j++) acc[i][j] = make_float4(0.f,0.f,0.f,0.f);

    #pragma unroll
    for (int s = 0; s < 2; s++) {
        #pragma unroll
        for (int t = 0; t < 8; t++) {
            int i = tid + 128*t; int kk = i & 15, m = i >> 4;
            cp4(&As[s][(kk & 3)*PLB + m*4 + (kk >> 2)], &A[(size_t)(m0 + m)*512 + s*16 + kk]);
            cp4(&Bs[s][(kk & 3)*PLB + m*4 + (kk >> 2)], &W[(size_t)(n0 + m)*512 + s*16 + kk]);
        }
        cp_commit();
    }

    for (int it = 0; it < 32; it++) {
        if (it < 31) cp_wait1(); else cp_wait0();
        __syncthreads();
        if (it + 2 < 32) {
            int k0 = (it + 2) * 16, buf = (it + 2) % 3;
            #pragma unroll
            for (int t = 0; t < 8; t++) {
                int i = tid + 128*t; int kk = i & 15, m = i >> 4;
                cp4(&As[buf][(kk & 3)*PLB + m*4 + (kk >> 2)], &A[(size_t)(m0 + m)*512 + k0 + kk]);
                cp4(&Bs[buf][(kk & 3)*PLB + m*4 + (kk >> 2)], &W[(size_t)(n0 + m)*512 + k0 + kk]);
            }
            cp_commit();
        }
        const float* a = As[it % 3];
        const float* bsm = Bs[it % 3];
        unsigned bu[4][4];
        #pragma unroll
        for (int j = 0; j < 4; j++) {
            float4 vv = *(const float4*)&bsm[c*PLB + (warp_n + j*8 + r)*4];
            bu[j][0]=f2t(vv.x); bu[j][1]=f2t(vv.y); bu[j][2]=f2t(vv.z); bu[j][3]=f2t(vv.w);
        }
        #pragma unroll
        for (int i = 0; i < 2; i++) {
            float4 lo = *(const float4*)&a[c*PLB + (warp_m + i*16 + r)*4];
            float4 hi = *(const float4*)&a[c*PLB + (warp_m + i*16 + r + 8)*4];
            unsigned a00=f2t(lo.x), a01=f2t(lo.y), a02=f2t(lo.z), a03=f2t(lo.w);
            unsigned a10=f2t(hi.x), a11=f2t(hi.y), a12=f2t(hi.z), a13=f2t(hi.w);
            #pragma unroll
            for (int j = 0; j < 4; j++) {
                mma8(acc[i][j], a00, a10, a01, a11, bu[j][0], bu[j][1]);
                mma8(acc[i][j], a02, a12, a03, a13, bu[j][2], bu[j][3]);
            }
        }
    }
    float scale = (z == 0) ? QSCALE : 1.0f;
    #pragma unroll
    for (int j = 0; j < 4; j++) {
        int dk = warp_n + j*8 + 2*c;
        float b0v = bias[n0 + dk], b1v = bias[n0 + dk + 1];
        #pragma unroll
        for (int i = 0; i < 2; i++) {
            float4 d = acc[i][j];
            int R0 = m0 + warp_m + i*16 + r;
            int R1 = R0 + 8;
            float2 o0 = make_float2(f2tf((d.x + b0v)*scale), f2tf((d.y + b1v)*scale));
            float2 o1 = make_float2(f2tf((d.z + b0v)*scale), f2tf((d.w + b1v)*scale));
            *(float2*)&dst[(((size_t)((R0 >> 9)*8 + h)*512 + (R0 & 511))*64) + dk] = o0;
            *(float2*)&dst[(((size_t)((R1 >> 9)*8 + h)*512 + (R1 & 511))*64) + dk] = o1;
        }
    }
}

// ---------------- edge bias + mask ----------------
__global__ void __launch_bounds__(256) biask_kernel(
    const float* __restrict__ edge, const unsigned char* __restrict__ mask,
    const float* __restrict__ W_eb, const float* __restrict__ b_eb) {
    __shared__ float w[32];
    __shared__ float b0s;
    if (threadIdx.x < 32) w[threadIdx.x] = W_eb[threadIdx.x];
    if (threadIdx.x == 0) b0s = b_eb[0];
    __syncthreads();
    int warp = threadIdx.x >> 5, lane = threadIdx.x & 31;
    int g = lane >> 3, sub = lane & 7;
    float w0 = w[sub*4], w1 = w[sub*4+1], w2 = w[sub*4+2], w3 = w[sub*4+3];
    size_t base = ((size_t)blockIdx.x * 8 + warp) * 64;
    for (int step = 0; step < 16; step++) {
        size_t pb = base + (size_t)step * 4;
        float4 ev = *(const float4*)(edge + (pb + g)*32 + sub*4);
        float t = ev.x*w0;
        t = fmaf(ev.y, w1, t); t = fmaf(ev.z, w2, t); t = fmaf(ev.w, w3, t);
        t += __shfl_xor_sync(0xffffffff, t, 4);
        t += __shfl_xor_sync(0xffffffff, t, 2);
        t += __shfl_xor_sync(0xffffffff, t, 1);
        if (sub == 0) {
            size_t p = pb + g;
            float r = (t + b0s) * BSCALE;
            g_bias[p] = mask[p] ? -INFINITY : r;
        }
    }
}

// ---------------- scores GEMM: S[n][m] = q.kT + bias (tf32 MMA) ------------
// grid (8, 8, 32): (m-tile, n-tile, bh). K=64 -> 4 k-iters.
__global__ void __launch_bounds__(128) sc_kernel() {
    __shared__ float As[3][4*PLB];
    __shared__ float Bs[3][4*PLB];
    int bh = blockIdx.z, b = bh >> 3;
    int n0 = blockIdx.y * 64, m0 = blockIdx.x * 64;
    const float* q = g_q + (size_t)bh*512*64 + (size_t)n0*64;
    const float* k = g_k + (size_t)bh*512*64 + (size_t)m0*64;
    int tid = threadIdx.x, lane = tid & 31, w = tid >> 5;
    int warp_m = (w & 1) * 32, warp_n = (w >> 1) * 32;
    int r = lane >> 2, c = lane & 3;

    float4 acc[2][4];
    #pragma unroll
    for (int i = 0; i < 2; i++)
        #pragma unroll
        for (int j = 0; j < 4; j++) acc[i][j] = make_float4(0.f,0.f,0.f,0.f);

    #pragma unroll
    for (int s = 0; s < 2; s++) {
        #pragma unroll
        for (int t = 0; t < 8; t++) {
            int i = tid + 128*t; int kk = i & 15, m = i >> 4;
            cp4(&As[s][(kk & 3)*PLB + m*4 + (kk >> 2)], &q[(size_t)m*64 + s*16 + kk]);
            cp4(&Bs[s][(kk & 3)*PLB + m*4 + (kk >> 2)], &k[(size_t)m*64 + s*16 + kk]);
        }
        cp_commit();
    }

    for (int it = 0; it < 4; it++) {
        if (it < 3) cp_wait1(); else cp_wait0();
        __syncthreads();
        if (it + 2 < 4) {
            int k0 = (it + 2) * 16, buf = (it + 2) % 3;
            #pragma unroll
            for (int t = 0; t < 8; t++) {
                int i = tid + 128*t; int kk = i & 15, m = i >> 4;
                cp4(&As[buf][(kk & 3)*PLB + m*4 + (kk >> 2)], &q[(size_t)m*64 + k0 + kk]);
                cp4(&Bs[buf][(kk & 3)*PLB + m*4 + (kk >> 2)], &k[(size_t)m*64 + k0 + kk]);
            }
            cp_commit();
        }
        gemm_stage_raw(As[it % 3], Bs[it % 3], warp_m, warp_n, r, c, acc);
    }
    // epilogue: S + bias -> g_p (fp32, unnormalized)
    #pragma unroll
    for (int j = 0; j < 4; j++) {
        int mcol = m0 + warp_n + j*8 + 2*c;
        #pragma unroll
        for (int i = 0; i < 2; i++) {
            float4 d = acc[i][j];
            int R0 = n0 + warp_m + i*16 + r;
            float2 bb0 = *(const float2*)&g_bias[((size_t)b*512 + R0)*512 + mcol];
            float2 bb1 = *(const float2*)&g_bias[((size_t)b*512 + R0 + 8)*512 + mcol];
            *(float2*)&g_p[((size_t)bh*512 + R0)*512 + mcol] =
                make_float2(d.x + bb0.x, d.y + bb0.y);
            *(float2*)&g_p[((size_t)bh*512 + R0 + 8)*512 + mcol] =
                make_float2(d.z + bb1.x, d.w + bb1.y);
        }
    }
}

// ---------------- softmax: warp per row, in place, writes tf32-rounded -----
__global__ void __launch_bounds__(256) softmax_kernel() {
    int row = blockIdx.x * 8 + (threadIdx.x >> 5);
    int lane = threadIdx.x & 31;
    float* p = g_p + (size_t)row * 512;
    float4 v[4];
    #pragma unroll
    for (int t = 0; t < 4; t++) v[t] = *(const float4*)(p + t*128 + lane*4);
    float mx = -INFINITY;
    #pragma unroll
    for (int t = 0; t < 4; t++)
        mx = fmaxf(mx, fmaxf(fmaxf(v[t].x, v[t].y), fmaxf(v[t].z, v[t].w)));
    #pragma unroll
    for (int off = 16; off > 0; off >>= 1)
        mx = fmaxf(mx, __shfl_xor_sync(0xffffffff, mx, off));
    float s = 0.f;
    #pragma unroll
    for (int t = 0; t < 4; t++) {
        v[t].x = __expf(v[t].x - mx); v[t].y = __expf(v[t].y - mx);
        v[t].z = __expf(v[t].z - mx); v[t].w = __expf(v[t].w - mx);
        s += v[t].x + v[t].y + v[t].z + v[t].w;
    }
    #pragma unroll
    for (int off = 16; off > 0; off >>= 1)
        s += __shfl_xor_sync(0xffffffff, s, off);
    float inv = 1.f / s;
    #pragma unroll
    for (int t = 0; t < 4; t++) {
        float4 o = make_float4(f2tf(v[t].x*inv), f2tf(v[t].y*inv),
                               f2tf(v[t].z*inv), f2tf(v[t].w*inv));
        *(float4*)(p + t*128 + lane*4) = o;
    }
}

// ---------------- context: tf32 MMA, 3-stage cp.async ----------------------
__global__ void __launch_bounds__(128) ctx_kernel() {
    __shared__ float As[3][4*PLB];
    __shared__ float Bs[3][4*PLB];
    int bh = blockIdx.y, b = bh >> 3, h = bh & 7;
    int n0 = blockIdx.x * 64;
    const float* p = g_p + (size_t)bh * 512 * 512;
    const float* v = g_v + (size_t)bh * 512 * 64;
    int tid = threadIdx.x, lane = tid & 31, w = tid >> 5;
    int warp_m = (w & 1) * 32, warp_n = (w >> 1) * 32;
    int r = lane >> 2, c = lane & 3;

    float4 acc[2][4];
    #pragma unroll
    for (int i = 0; i < 2; i++)
        #pragma unroll
        for (int j = 0; j < 4; j++) acc[i][j] = make_float4(0.f,0.f,0.f,0.f);

    #pragma unroll
    for (int s = 0; s < 2; s++) {
        #pragma unroll
        for (int t = 0; t < 8; t++) {
            int i = tid + 128*t; int kk = i & 15, m = i >> 4;
            cp4(&As[s][(kk & 3)*PLB + m*4 + (kk >> 2)], &p[(size_t)(n0 + m)*512 + s*16 + kk]);
        }
        #pragma unroll
        for (int t = 0; t < 8; t++) {
            int i = tid + 128*t; int n = i & 63, kk = i >> 6;
            cp4(&Bs[s][(kk & 3)*PLB + n*4 + (kk >> 2)], &v[(size_t)(s*16 + kk)*64 + n]);
        }
        cp_commit();
    }

    for (int it = 0; it < 32; it++) {
        if (it < 31) cp_wait1(); else cp_wait0();
        __syncthreads();
        if (it + 2 < 32) {
            int k0 = (it + 2) * 16, buf = (it + 2) % 3;
            #pragma unroll
            for (int t = 0; t < 8; t++) {
                int i = tid + 128*t; int kk = i & 15, m = i >> 4;
                cp4(&As[buf][(kk & 3)*PLB + m*4 + (kk >> 2)], &p[(size_t)(n0 + m)*512 + k0 + kk]);
            }
            #pragma unroll
            for (int t = 0; t < 8; t++) {
                int i = tid + 128*t; int n = i & 63, kk = i >> 6;
                cp4(&Bs[buf][(kk & 3)*PLB + n*4 + (kk >> 2)], &v[(size_t)(k0 + kk)*64 + n]);
            }
            cp_commit();
        }
        gemm_stage_raw(As[it % 3], Bs[it % 3], warp_m, warp_n, r, c, acc);
    }
    #pragma unroll
    for (int j = 0; j < 4; j++) {
        int dk = warp_n + j*8 + 2*c;
        #pragma unroll
        for (int i = 0; i < 2; i++) {
            float4 d = acc[i][j];
            int R0 = n0 + warp_m + i*16 + r;
            *(float2*)&g_s1[((size_t)b*512 + R0)*768 + h*64 + dk] =
                make_float2(f2tf(d.x), f2tf(d.y));
            *(float2*)&g_s1[((size_t)b*512 + R0 + 8)*768 + h*64 + dk] =
                make_float2(f2tf(d.z), f2tf(d.w));
        }
    }
}

// ---------------- E accumulation: warp = n-row, lanes = e ------------------
__global__ void __launch_bounds__(256) e_kernel(const float* __restrict__ edge) {
    __shared__ float sP[32*68];   // [mm][np*8+h]
    int tid = threadIdx.x;
    int np = tid >> 5, e = tid & 31;
    int b = blockIdx.y, n0 = blockIdx.x * 8;
    int n = n0 + np;
    const float* ep = edge + ((size_t)(b*512 + n) * 512) * 32 + e;
    float2 acc[4];
    #pragma unroll
    for (int j = 0; j < 4; j++) acc[j] = make_float2(0.f, 0.f);

    for (int c = 0; c < 16; c++) {
        __syncthreads();
        #pragma unroll
        for (int i = 0; i < 2; i++) {
            int idx = tid + 256*i;
            int rr = idx >> 3, seg = idx & 7;
            int hh = rr & 7, nn = rr >> 3;
            float4 v = *(const float4*)&g_p[(((size_t)(b*8 + hh)*512) + n0 + nn)*512 + c*32 + seg*4];
            sP[(seg*4+0)*68 + nn*8 + hh] = v.x;
            sP[(seg*4+1)*68 + nn*8 + hh] = v.y;
            sP[(seg*4+2)*68 + nn*8 + hh] = v.z;
            sP[(seg*4+3)*68 + nn*8 + hh] = v.w;
        }
        __syncthreads();
        #pragma unroll 4
        for (int mm = 0; mm < 32; mm++) {
            float ev = __ldg(ep + (size_t)(c*32 + mm) * 32);
            float2 ee = make_float2(ev, ev);
            float4 p0 = *(const float4*)&sP[mm*68 + np*8];
            float4 p1 = *(const float4*)&sP[mm*68 + np*8 + 4];
            ffma2(acc[0], make_float2(p0.x, p0.y), ee);
            ffma2(acc[1], make_float2(p0.z, p0.w), ee);
            ffma2(acc[2], make_float2(p1.x, p1.y), ee);
            ffma2(acc[3], make_float2(p1.z, p1.w), ee);
        }
    }
    float* o = &g_s1[((size_t)b*512 + n)*768 + 512];
    o[0*32 + e] = f2tf(acc[0].x); o[1*32 + e] = f2tf(acc[0].y);
    o[2*32 + e] = f2tf(acc[1].x); o[3*32 + e] = f2tf(acc[1].y);
    o[4*32 + e] = f2tf(acc[2].x); o[5*32 + e] = f2tf(acc[2].y);
    o[6*32 + e] = f2tf(acc[3].x); o[7*32 + e] = f2tf(acc[3].y);
}

// ---------------- final GEMM: tf32 MMA, 3-stage cp.async -------------------
__global__ void __launch_bounds__(128) final_kernel(float* __restrict__ out) {
    __shared__ float As[3][4*PLB];
    __shared__ float Bs[3][4*PLB];
    int m0 = blockIdx.y * 64, n0 = blockIdx.x * 64;
    int tid = threadIdx.x, lane = tid & 31, w = tid >> 5;
    int warp_m = (w & 1) * 32, warp_n = (w >> 1) * 32;
    int r = lane >> 2, c = lane & 3;

    float4 acc[2][4];
    #pragma unroll
    for (int i = 0; i < 2; i++)
        #pragma unroll
        for (int j = 0; j < 4; j++) acc[i][j] = make_float4(0.f,0.f,0.f,0.f);

    #pragma unroll
    for (int s = 0; s < 2; s++) {
        #pragma unroll
        for (int t = 0; t < 8; t++) {
            int i = tid + 128*t; int kk = i & 15, m = i >> 4;
            cp4(&As[s][(kk & 3)*PLB + m*4 + (kk >> 2)], &g_s1[(size_t)(m0 + m)*768 + s*16 + kk]);
            cp4(&Bs[s][(kk & 3)*PLB + m*4 + (kk >> 2)], &g_wcomb[(size_t)(n0 + m)*768 + s*16 + kk]);
        }
        cp_commit();
    }

    for (int it = 0; it < 48; it++) {
        if (it < 47) cp_wait1(); else cp_wait0();
        __syncthreads();
        if (it + 2 < 48) {
            int k0 = (it + 2) * 16, buf = (it + 2) % 3;
            #pragma unroll
            for (int t = 0; t < 8; t++) {
                int i = tid + 128*t; int kk = i & 15, m = i >> 4;
                cp4(&As[buf][(kk & 3)*PLB + m*4 + (kk >> 2)], &g_s1[(size_t)(m0 + m)*768 + k0 + kk]);
                cp4(&Bs[buf][(kk & 3)*PLB + m*4 + (kk >> 2)], &g_wcomb[(size_t)(n0 + m)*768 + k0 + kk]);
            }
            cp_commit();
        }
        gemm_stage_raw(As[it % 3], Bs[it % 3], warp_m, warp_n, r, c, acc);
    }
    #pragma unroll
    for (int j = 0; j < 4; j++) {
        int np0 = n0 + warp_n + j*8 + 2*c;
        float b0v = g_bfinal[np0], b1v = g_bfinal[np0 + 1];
        #pragma unroll
        for (int i = 0; i < 2; i++) {
            float4 d = acc[i][j];
            int R0 = m0 + warp_m + i*16 + r;
            *(float2*)&out[(size_t)R0*512 + np0] = make_float2(d.x + b0v, d.y + b1v);
            *(float2*)&out[(size_t)(R0 + 8)*512 + np0] = make_float2(d.z + b0v, d.w + b1v);
        }
    }
}

extern "C" void kernel_launch(void* const* d_in, const int* in_sizes, int n_in,
                              void* d_out, int out_size) {
    const float* Q    = (const float*)d_in[0];
    const float* K    = (const float*)d_in[1];
    const float* V    = (const float*)d_in[2];
    const unsigned char* mask = (const unsigned char*)d_in[3];
    const float* edge = (const float*)d_in[4];
    const float* W_Q  = (const float*)d_in[5];
    const float* b_Q  = (const float*)d_in[6];
    const float* W_K  = (const float*)d_in[7];
    const float* b_K  = (const float*)d_in[8];
    const float* W_V  = (const float*)d_in[9];
    const float* b_V  = (const float*)d_in[10];
    const float* W_Ke = (const float*)d_in[11];
    const float* b_Ke = (const float*)d_in[12];
    const float* W_eb = (const float*)d_in[13];
    const float* b_eb = (const float*)d_in[14];
    const float* W_eo = (const float*)d_in[15];
    const float* b_eo = (const float*)d_in[16];
    const float* W_o  = (const float*)d_in[17];
    const float* b_o  = (const float*)d_in[18];
    float* out = (float*)d_out;

    static cudaStream_t s1 = nullptr;
    static cudaEvent_t evF, evB, evS, evE;
    if (!s1) {
        cudaStreamCreateWithFlags(&s1, cudaStreamNonBlocking);
        cudaEventCreateWithFlags(&evF, cudaEventDisableTiming);
        cudaEventCreateWithFlags(&evB, cudaEventDisableTiming);
        cudaEventCreateWithFlags(&evS, cudaEventDisableTiming);
        cudaEventCreateWithFlags(&evE, cudaEventDisableTiming);
    }

    //   s1:   biask -> prep1 -> prep2 -> (wait evS) e
    //   main: proj -> (wait evB) sc -> softmax -> ctx -> (wait evE) final
    cudaEventRecord(evF, 0);
    cudaStreamWaitEvent(s1, evF, 0);
    biask_kernel<<<2048, 256, 0, s1>>>(edge, mask, W_eb, b_eb);          // 1
    cudaEventRecord(evB, s1);
    proj_kernel<<<dim3(8, 32, 3), 128>>>(Q, K, V, W_Q, W_K, W_V, b_Q, b_K, b_V); // 2
    prep1_kernel<<<512, 256, 0, s1>>>(W_Ke, b_Ke, W_eo, b_eo);           // 3
    cudaStreamWaitEvent(0, evB, 0);
    sc_kernel<<<dim3(8, 8, 32), 128>>>();                                 // 4 (profiled)
    softmax_kernel<<<2048, 256>>>();                                      // 5
    prep2_kernel<<<512, 64, 0, s1>>>(W_o, b_o);                           // 6
    cudaEventRecord(evS, 0);
    cudaStreamWaitEvent(s1, evS, 0);
    e_kernel<<<dim3(64, 4), 256, 0, s1>>>(edge);                          // 7
    ctx_kernel<<<dim3(8, 32), 128>>>();                                   // 8
    cudaEventRecord(evE, s1);
    cudaStreamWaitEvent(0, evE, 0);
    final_kernel<<<dim3(8, 32), 128>>>(out);                              // 9
}

// round 17
// speedup vs baseline: 1.0550x; 1.0550x over previous
#include <cuda_runtime.h>
#include <math.h>
#include <stdint.h>

#define QSCALE 0.08838834764831845f   // (2*64)^-0.5
#define BSCALE 0.7071067811865476f    // 2^-0.5

// ---------------- device scratch ----------------
// Plane-tiled operands: tile = 64 rows x 16 k, 1056 floats:
//   word(row,k) = (k&3)*264 + (row&63)*4 + ((k>>2)&3)
__device__ float g_q[4*8*512*64];
__device__ float g_k[4*8*512*64];
__device__ float g_v[32*32*1056];      // [bh][m-tile] plane-tiled, rows=dk, k=m
__device__ float g_bias[4*512*512];
__device__ float g_p[4*8*512*512];     // tf32-rounded P (row-major)
__device__ float g_s1[32*48*1056];     // [rowblk][ktile] plane-tiled
__device__ float g_wcomb[8*48*1056];   // [dblk][ktile] plane-tiled
__device__ float g_bfinal[512];
__device__ float g_M[512*256];
__device__ float g_c[512];

// ---------------- packed fp32x2 FMA ----------------
__device__ __forceinline__ void ffma2(float2& c, float2 a, float2 b) {
    unsigned long long ca = *reinterpret_cast<const unsigned long long*>(&a);
    unsigned long long cb = *reinterpret_cast<const unsigned long long*>(&b);
    unsigned long long cc = *reinterpret_cast<unsigned long long*>(&c);
    asm("fma.rn.f32x2 %0, %1, %2, %0;" : "+l"(cc) : "l"(ca), "l"(cb));
    *reinterpret_cast<unsigned long long*>(&c) = cc;
}

// ---------------- tf32 helpers ----------------
__device__ __forceinline__ unsigned f2t(float x) {
    unsigned u; asm("cvt.rna.tf32.f32 %0, %1;" : "=r"(u) : "f"(x)); return u;
}
__device__ __forceinline__ float f2tf(float x) {
    return __uint_as_float(f2t(x));
}
__device__ __forceinline__ void mma8(float4& d, unsigned a0, unsigned a1, unsigned a2, unsigned a3,
                                     unsigned b0, unsigned b1) {
    asm volatile("mma.sync.aligned.m16n8k8.row.col.f32.tf32.tf32.f32 "
                 "{%0,%1,%2,%3},{%4,%5,%6,%7},{%8,%9},{%0,%1,%2,%3};"
                 : "+f"(d.x), "+f"(d.y), "+f"(d.z), "+f"(d.w)
                 : "r"(a0), "r"(a1), "r"(a2), "r"(a3), "r"(b0), "r"(b1));
}

// ---------------- cp.async helpers ----------------
__device__ __forceinline__ void cp4(void* s, const void* g) {
    unsigned sa = (unsigned)__cvta_generic_to_shared(s);
    asm volatile("cp.async.ca.shared.global [%0], [%1], 4;" :: "r"(sa), "l"(g));
}
__device__ __forceinline__ void cp16(void* s, const void* g) {
    unsigned sa = (unsigned)__cvta_generic_to_shared(s);
    asm volatile("cp.async.cg.shared.global [%0], [%1], 16;" :: "r"(sa), "l"(g));
}
__device__ __forceinline__ void cp_commit() { asm volatile("cp.async.commit_group;"); }
__device__ __forceinline__ void cp_wait1()  { asm volatile("cp.async.wait_group 1;"); }
__device__ __forceinline__ void cp_wait0()  { asm volatile("cp.async.wait_group 0;"); }

#define PLB 264   // plane stride (words)
#define TILE 1056 // floats per stage tile (4 planes)

// copy one pre-swizzled 1056-float tile gmem->smem (128 threads, 264 x 16B)
__device__ __forceinline__ void tstage(float* dst, const float* src, int tid) {
    cp16(dst + tid*4,        src + tid*4);
    cp16(dst + (tid+128)*4,  src + (tid+128)*4);
    if (tid < 8) cp16(dst + (256+tid)*4, src + (256+tid)*4);
}

// plane-tile word address within a tile
__device__ __forceinline__ int pword(int row, int k) {
    return (k & 3)*PLB + (row & 63)*4 + ((k >> 2) & 3);
}

// Fragment stage for pre-rounded data: raw uint4 loads, no CVT.
__device__ __forceinline__ void gemm_stage_raw(const float* a, const float* bsm,
                                               int warp_m, int warp_n, int r, int c,
                                               float4 (&acc)[2][4]) {
    const unsigned* au = (const unsigned*)a;
    const unsigned* bu_ = (const unsigned*)bsm;
    uint4 bu[4];
    #pragma unroll
    for (int j = 0; j < 4; j++)
        bu[j] = *(const uint4*)&bu_[c*PLB + (warp_n + j*8 + r)*4];
    #pragma unroll
    for (int i = 0; i < 2; i++) {
        uint4 lo = *(const uint4*)&au[c*PLB + (warp_m + i*16 + r)*4];
        uint4 hi = *(const uint4*)&au[c*PLB + (warp_m + i*16 + r + 8)*4];
        #pragma unroll
        for (int j = 0; j < 4; j++) {
            mma8(acc[i][j], lo.x, hi.x, lo.y, hi.y, bu[j].x, bu[j].y);
            mma8(acc[i][j], lo.z, hi.z, lo.w, hi.w, bu[j].z, bu[j].w);
        }
    }
}

// ---------------- prep ----------------
__global__ void prep1_kernel(const float* __restrict__ W_Ke, const float* __restrict__ b_Ke,
                             const float* __restrict__ W_eo, const float* __restrict__ b_eo) {
    int d2 = blockIdx.x, j = threadIdx.x;
    int h = j >> 5, e = j & 31;
    const float* weo = W_eo + d2 * 256;
    float acc = 0.f;
    #pragma unroll
    for (int de = 0; de < 32; de++)
        acc = fmaf(weo[h*32 + de], W_Ke[de*32 + e], acc);
    g_M[d2*256 + j] = acc;
    if (j == 0) {
        float c = b_eo[d2];
        for (int jj = 0; jj < 256; jj++) c = fmaf(weo[jj], b_Ke[jj & 31], c);
        g_c[d2] = c;
    }
}

__device__ __forceinline__ void store_wc(int d, int k, float v) {
    g_wcomb[((size_t)(d >> 6)*48 + (k >> 4))*TILE + pword(d, k)] = v;
}

__global__ void prep2_kernel(const float* __restrict__ W_o, const float* __restrict__ b_o) {
    int d = blockIdx.x, j4 = threadIdx.x;   // 0..63
    const float* wo = W_o + (size_t)d * 1024;
    float4 acc = make_float4(0.f,0.f,0.f,0.f);
    float bacc = 0.f;
    #pragma unroll 4
    for (int d2 = 0; d2 < 512; d2++) {
        float wv = wo[512 + d2];
        float4 m = *(const float4*)&g_M[d2*256 + j4*4];
        acc.x = fmaf(wv, m.x, acc.x); acc.y = fmaf(wv, m.y, acc.y);
        acc.z = fmaf(wv, m.z, acc.z); acc.w = fmaf(wv, m.w, acc.w);
        if (j4 == 0) bacc = fmaf(wv, g_c[d2], bacc);
    }
    store_wc(d, 512 + j4*4 + 0, f2tf(acc.x));
    store_wc(d, 512 + j4*4 + 1, f2tf(acc.y));
    store_wc(d, 512 + j4*4 + 2, f2tf(acc.z));
    store_wc(d, 512 + j4*4 + 3, f2tf(acc.w));
    #pragma unroll
    for (int t = 0; t < 8; t++)
        store_wc(d, j4*8 + t, f2tf(wo[j4*8 + t]));
    if (j4 == 0) g_bfinal[d] = b_o[d] + bacc;
}

// ---------------- QKV projection: tf32 MMA, 3-stage cp.async, CTA 64x64 ----
// grid (8, 32, 3). q/k row-major (tf32-rounded); v plane-tiled transposed.
__global__ void __launch_bounds__(128) proj_kernel(
    const float* __restrict__ Q, const float* __restrict__ K, const float* __restrict__ V,
    const float* __restrict__ WQ, const float* __restrict__ WK, const float* __restrict__ WV,
    const float* __restrict__ bQ, const float* __restrict__ bK, const float* __restrict__ bV) {
    __shared__ float As[3][TILE];
    __shared__ float Bs[3][TILE];
    int z = blockIdx.z;
    const float* A    = (z == 0) ? Q  : (z == 1) ? K  : V;
    const float* W    = (z == 0) ? WQ : (z == 1) ? WK : WV;
    const float* bias = (z == 0) ? bQ : (z == 1) ? bK : bV;
    int m0 = blockIdx.y * 64, n0 = blockIdx.x * 64;
    int tid = threadIdx.x, lane = tid & 31, w = tid >> 5;
    int warp_m = (w & 1) * 32, warp_n = (w >> 1) * 32;
    int r = lane >> 2, c = lane & 3;
    int h = blockIdx.x;

    float4 acc[2][4];
    #pragma unroll
    for (int i = 0; i < 2; i++)
        #pragma unroll
        for (int j = 0; j < 4; j++) acc[i][j] = make_float4(0.f,0.f,0.f,0.f);

    #pragma unroll
    for (int s = 0; s < 2; s++) {
        #pragma unroll
        for (int t = 0; t < 8; t++) {
            int i = tid + 128*t; int kk = i & 15, m = i >> 4;
            cp4(&As[s][(kk & 3)*PLB + m*4 + (kk >> 2)], &A[(size_t)(m0 + m)*512 + s*16 + kk]);
            cp4(&Bs[s][(kk & 3)*PLB + m*4 + (kk >> 2)], &W[(size_t)(n0 + m)*512 + s*16 + kk]);
        }
        cp_commit();
    }

    for (int it = 0; it < 32; it++) {
        if (it < 31) cp_wait1(); else cp_wait0();
        __syncthreads();
        if (it + 2 < 32) {
            int k0 = (it + 2) * 16, buf = (it + 2) % 3;
            #pragma unroll
            for (int t = 0; t < 8; t++) {
                int i = tid + 128*t; int kk = i & 15, m = i >> 4;
                cp4(&As[buf][(kk & 3)*PLB + m*4 + (kk >> 2)], &A[(size_t)(m0 + m)*512 + k0 + kk]);
                cp4(&Bs[buf][(kk & 3)*PLB + m*4 + (kk >> 2)], &W[(size_t)(n0 + m)*512 + k0 + kk]);
            }
            cp_commit();
        }
        const float* a = As[it % 3];
        const float* bsm = Bs[it % 3];
        unsigned bu[4][4];
        #pragma unroll
        for (int j = 0; j < 4; j++) {
            float4 vv = *(const float4*)&bsm[c*PLB + (warp_n + j*8 + r)*4];
            bu[j][0]=f2t(vv.x); bu[j][1]=f2t(vv.y); bu[j][2]=f2t(vv.z); bu[j][3]=f2t(vv.w);
        }
        #pragma unroll
        for (int i = 0; i < 2; i++) {
            float4 lo = *(const float4*)&a[c*PLB + (warp_m + i*16 + r)*4];
            float4 hi = *(const float4*)&a[c*PLB + (warp_m + i*16 + r + 8)*4];
            unsigned a00=f2t(lo.x), a01=f2t(lo.y), a02=f2t(lo.z), a03=f2t(lo.w);
            unsigned a10=f2t(hi.x), a11=f2t(hi.y), a12=f2t(hi.z), a13=f2t(hi.w);
            #pragma unroll
            for (int j = 0; j < 4; j++) {
                mma8(acc[i][j], a00, a10, a01, a11, bu[j][0], bu[j][1]);
                mma8(acc[i][j], a02, a12, a03, a13, bu[j][2], bu[j][3]);
            }
        }
    }
    if (z == 2) {
        // v plane-tiled: rows = dk, k = token m (per bh)
        #pragma unroll
        for (int j = 0; j < 4; j++) {
            int dk = warp_n + j*8 + 2*c;
            float b0v = bias[n0 + dk], b1v = bias[n0 + dk + 1];
            #pragma unroll
            for (int i = 0; i < 2; i++) {
                float4 d = acc[i][j];
                int R0 = m0 + warp_m + i*16 + r;
                int b = R0 >> 9, s = R0 & 511;
                size_t tb = ((size_t)(b*8 + h)*32 + (s >> 4))*TILE;
                g_v[tb + pword(dk,   s)]     = f2tf(d.x + b0v);
                g_v[tb + pword(dk+1, s)]     = f2tf(d.y + b1v);
                g_v[tb + pword(dk,   s + 8)] = f2tf(d.z + b0v);
                g_v[tb + pword(dk+1, s + 8)] = f2tf(d.w + b1v);
            }
        }
    } else {
        float* dst = (z == 0) ? g_q : g_k;
        float scale = (z == 0) ? QSCALE : 1.0f;
        #pragma unroll
        for (int j = 0; j < 4; j++) {
            int dk = warp_n + j*8 + 2*c;
            float b0v = bias[n0 + dk], b1v = bias[n0 + dk + 1];
            #pragma unroll
            for (int i = 0; i < 2; i++) {
                float4 d = acc[i][j];
                int R0 = m0 + warp_m + i*16 + r;
                int R1 = R0 + 8;
                float2 o0 = make_float2((d.x + b0v)*scale, (d.y + b1v)*scale);
                float2 o1 = make_float2((d.z + b0v)*scale, (d.w + b1v)*scale);
                *(float2*)&dst[(((size_t)((R0 >> 9)*8 + h)*512 + (R0 & 511))*64) + dk] = o0;
                *(float2*)&dst[(((size_t)((R1 >> 9)*8 + h)*512 + (R1 & 511))*64) + dk] = o1;
            }
        }
    }
}

// ---------------- edge bias + mask ----------------
__global__ void __launch_bounds__(256) biask_kernel(
    const float* __restrict__ edge, const unsigned char* __restrict__ mask,
    const float* __restrict__ W_eb, const float* __restrict__ b_eb) {
    __shared__ float w[32];
    __shared__ float b0s;
    if (threadIdx.x < 32) w[threadIdx.x] = W_eb[threadIdx.x];
    if (threadIdx.x == 0) b0s = b_eb[0];
    __syncthreads();
    int warp = threadIdx.x >> 5, lane = threadIdx.x & 31;
    int g = lane >> 3, sub = lane & 7;
    float w0 = w[sub*4], w1 = w[sub*4+1], w2 = w[sub*4+2], w3 = w[sub*4+3];
    size_t base = ((size_t)blockIdx.x * 8 + warp) * 64;
    for (int step = 0; step < 16; step++) {
        size_t pb = base + (size_t)step * 4;
        float4 ev = *(const float4*)(edge + (pb + g)*32 + sub*4);
        float t = ev.x*w0;
        t = fmaf(ev.y, w1, t); t = fmaf(ev.z, w2, t); t = fmaf(ev.w, w3, t);
        t += __shfl_xor_sync(0xffffffff, t, 4);
        t += __shfl_xor_sync(0xffffffff, t, 2);
        t += __shfl_xor_sync(0xffffffff, t, 1);
        if (sub == 0) {
            size_t p = pb + g;
            float r = (t + b0s) * BSCALE;
            g_bias[p] = mask[p] ? -INFINITY : r;
        }
    }
}

// ---------------- scores + softmax fused (R15 version) ---------------------
__global__ void __launch_bounds__(256) scores_kernel() {
    __shared__ float Qs[64][33];
    __shared__ float Ks[16][522];
    int bh = blockIdx.y, b = bh >> 3;
    int n0 = blockIdx.x * 32;
    const float* q = g_q + (size_t)bh * 512 * 64;
    const float* k = g_k + (size_t)bh * 512 * 64;
    int tid = threadIdx.x, w = tid >> 5, lane = tid & 31;

    for (int i = tid; i < 2048; i += 256) {
        int kk = i & 63, n = i >> 6;
        Qs[kk][n] = q[(size_t)(n0 + n)*64 + kk];
    }
    float2 acc[4][8];
    #pragma unroll
    for (int i = 0; i < 4; i++)
        #pragma unroll
        for (int j = 0; j < 8; j++) acc[i][j] = make_float2(0.f, 0.f);

    for (int c = 0; c < 4; c++) {
        __syncthreads();
        for (int i = tid; i < 2048; i += 256) {
            int kq = i & 3, m = i >> 2;
            float4 v = *(const float4*)&k[(size_t)m*64 + c*16 + kq*4];
            Ks[kq*4+0][m] = v.x; Ks[kq*4+1][m] = v.y;
            Ks[kq*4+2][m] = v.z; Ks[kq*4+3][m] = v.w;
        }
        __syncthreads();
        #pragma unroll
        for (int kk = 0; kk < 16; kk++) {
            float2 aa[4];
            #pragma unroll
            for (int i = 0; i < 4; i++) {
                float a = Qs[c*16+kk][w*4+i];
                aa[i] = make_float2(a, a);
            }
            #pragma unroll
            for (int jp = 0; jp < 8; jp++) {
                float2 bb = *(const float2*)&Ks[kk][jp*64 + lane*2];
                ffma2(acc[0][jp], aa[0], bb);
                ffma2(acc[1][jp], aa[1], bb);
                ffma2(acc[2][jp], aa[2], bb);
                ffma2(acc[3][jp], aa[3], bb);
            }
        }
    }
    #pragma unroll
    for (int i = 0; i < 4; i++) {
        int n = n0 + w*4 + i;
        const float* bp = &g_bias[((size_t)b*512 + n)*512];
        #pragma unroll
        for (int jp = 0; jp < 8; jp++) {
            float2 bb = *(const float2*)&bp[jp*64 + lane*2];
            acc[i][jp].x += bb.x;
            acc[i][jp].y += bb.y;
        }
        float mx = -INFINITY;
        #pragma unroll
        for (int jp = 0; jp < 8; jp++)
            mx = fmaxf(mx, fmaxf(acc[i][jp].x, acc[i][jp].y));
        #pragma unroll
        for (int off = 16; off > 0; off >>= 1)
            mx = fmaxf(mx, __shfl_xor_sync(0xffffffff, mx, off));
        float s = 0.f;
        #pragma unroll
        for (int jp = 0; jp < 8; jp++) {
            acc[i][jp].x = __expf(acc[i][jp].x - mx);
            acc[i][jp].y = __expf(acc[i][jp].y - mx);
            s += acc[i][jp].x + acc[i][jp].y;
        }
        #pragma unroll
        for (int off = 16; off > 0; off >>= 1)
            s += __shfl_xor_sync(0xffffffff, s, off);
        float inv = 1.f / s;
        float* pr = &g_p[((size_t)bh*512 + n)*512];
        #pragma unroll
        for (int jp = 0; jp < 8; jp++) {
            float2 o = make_float2(f2tf(acc[i][jp].x * inv), f2tf(acc[i][jp].y * inv));
            *(float2*)&pr[jp*64 + lane*2] = o;
        }
    }
}

// ---------------- context: A=P (cp4), B=v (pre-swizzled cp16) --------------
__global__ void __launch_bounds__(128) ctx_kernel() {
    __shared__ float As[3][TILE];
    __shared__ float Bs[3][TILE];
    int bh = blockIdx.y, b = bh >> 3, h = bh & 7;
    int n0 = blockIdx.x * 64;
    const float* p = g_p + (size_t)bh * 512 * 512;
    const float* vt = g_v + (size_t)bh * 32 * TILE;
    int tid = threadIdx.x, lane = tid & 31, w = tid >> 5;
    int warp_m = (w & 1) * 32, warp_n = (w >> 1) * 32;
    int r = lane >> 2, c = lane & 3;

    float4 acc[2][4];
    #pragma unroll
    for (int i = 0; i < 2; i++)
        #pragma unroll
        for (int j = 0; j < 4; j++) acc[i][j] = make_float4(0.f,0.f,0.f,0.f);

    #pragma unroll
    for (int s = 0; s < 2; s++) {
        #pragma unroll
        for (int t = 0; t < 8; t++) {
            int i = tid + 128*t; int kk = i & 15, m = i >> 4;
            cp4(&As[s][(kk & 3)*PLB + m*4 + (kk >> 2)], &p[(size_t)(n0 + m)*512 + s*16 + kk]);
        }
        tstage(Bs[s], vt + (size_t)s*TILE, tid);
        cp_commit();
    }

    for (int it = 0; it < 32; it++) {
        if (it < 31) cp_wait1(); else cp_wait0();
        __syncthreads();
        if (it + 2 < 32) {
            int k0 = (it + 2) * 16, buf = (it + 2) % 3;
            #pragma unroll
            for (int t = 0; t < 8; t++) {
                int i = tid + 128*t; int kk = i & 15, m = i >> 4;
                cp4(&As[buf][(kk & 3)*PLB + m*4 + (kk >> 2)], &p[(size_t)(n0 + m)*512 + k0 + kk]);
            }
            tstage(Bs[buf], vt + (size_t)(it + 2)*TILE, tid);
            cp_commit();
        }
        gemm_stage_raw(As[it % 3], Bs[it % 3], warp_m, warp_n, r, c, acc);
    }
    // epilogue: plane-tiled s1 (ctx part: dims h*64+dk)
    #pragma unroll
    for (int j = 0; j < 4; j++) {
        int dk = warp_n + j*8 + 2*c;
        int d0 = h*64 + dk;
        #pragma unroll
        for (int i = 0; i < 2; i++) {
            float4 d = acc[i][j];
            int R0 = n0 + warp_m + i*16 + r;
            size_t row0 = (size_t)b*512 + R0;
            size_t tb0 = ((row0 >> 6)*48 + (d0 >> 4))*TILE;
            size_t tb1 = (((row0 + 8) >> 6)*48 + (d0 >> 4))*TILE;
            g_s1[tb0 + pword((int)(row0 & 63), d0)]       = f2tf(d.x);
            g_s1[tb0 + pword((int)(row0 & 63), d0 + 1)]   = f2tf(d.y);
            g_s1[tb1 + pword((int)((row0+8) & 63), d0)]   = f2tf(d.z);
            g_s1[tb1 + pword((int)((row0+8) & 63), d0+1)] = f2tf(d.w);
        }
    }
}

// ---------------- E accumulation: warp = n-row, lanes = e ------------------
__global__ void __launch_bounds__(256) e_kernel(const float* __restrict__ edge) {
    __shared__ float sP[32*68];   // [mm][np*8+h]
    int tid = threadIdx.x;
    int np = tid >> 5, e = tid & 31;
    int b = blockIdx.y, n0 = blockIdx.x * 8;
    int n = n0 + np;
    const float* ep = edge + ((size_t)(b*512 + n) * 512) * 32 + e;
    float2 acc[4];
    #pragma unroll
    for (int j = 0; j < 4; j++) acc[j] = make_float2(0.f, 0.f);

    for (int c = 0; c < 16; c++) {
        __syncthreads();
        #pragma unroll
        for (int i = 0; i < 2; i++) {
            int idx = tid + 256*i;
            int rr = idx >> 3, seg = idx & 7;
            int hh = rr & 7, nn = rr >> 3;
            float4 v = *(const float4*)&g_p[(((size_t)(b*8 + hh)*512) + n0 + nn)*512 + c*32 + seg*4];
            sP[(seg*4+0)*68 + nn*8 + hh] = v.x;
            sP[(seg*4+1)*68 + nn*8 + hh] = v.y;
            sP[(seg*4+2)*68 + nn*8 + hh] = v.z;
            sP[(seg*4+3)*68 + nn*8 + hh] = v.w;
        }
        __syncthreads();
        #pragma unroll 4
        for (int mm = 0; mm < 32; mm++) {
            float ev = __ldg(ep + (size_t)(c*32 + mm) * 32);
            float2 ee = make_float2(ev, ev);
            float4 p0 = *(const float4*)&sP[mm*68 + np*8];
            float4 p1 = *(const float4*)&sP[mm*68 + np*8 + 4];
            ffma2(acc[0], make_float2(p0.x, p0.y), ee);
            ffma2(acc[1], make_float2(p0.z, p0.w), ee);
            ffma2(acc[2], make_float2(p1.x, p1.y), ee);
            ffma2(acc[3], make_float2(p1.z, p1.w), ee);
        }
    }
    // epilogue: plane-tiled s1 (E part: dims 512 + h2*32 + e)
    size_t row = (size_t)b*512 + n;
    float vals[8] = {acc[0].x, acc[0].y, acc[1].x, acc[1].y,
                     acc[2].x, acc[2].y, acc[3].x, acc[3].y};
    #pragma unroll
    for (int h2 = 0; h2 < 8; h2++) {
        int d = 512 + h2*32 + e;
        size_t tb = ((row >> 6)*48 + (d >> 4))*TILE;
        g_s1[tb + pword((int)(row & 63), d)] = f2tf(vals[h2]);
    }
}

// ---------------- final GEMM: both operands pre-swizzled (cp16) ------------
__global__ void __launch_bounds__(128) final_kernel(float* __restrict__ out) {
    __shared__ float As[3][TILE];
    __shared__ float Bs[3][TILE];
    int m0 = blockIdx.y * 64, n0 = blockIdx.x * 64;
    const float* at = g_s1    + (size_t)(m0 >> 6)*48*TILE;
    const float* bt = g_wcomb + (size_t)(n0 >> 6)*48*TILE;
    int tid = threadIdx.x, lane = tid & 31, w = tid >> 5;
    int warp_m = (w & 1) * 32, warp_n = (w >> 1) * 32;
    int r = lane >> 2, c = lane & 3;

    float4 acc[2][4];
    #pragma unroll
    for (int i = 0; i < 2; i++)
        #pragma unroll
        for (int j = 0; j < 4; j++) acc[i][j] = make_float4(0.f,0.f,0.f,0.f);

    #pragma unroll
    for (int s = 0; s < 2; s++) {
        tstage(As[s], at + (size_t)s*TILE, tid);
        tstage(Bs[s], bt + (size_t)s*TILE, tid);
        cp_commit();
    }

    for (int it = 0; it < 48; it++) {
        if (it < 47) cp_wait1(); else cp_wait0();
        __syncthreads();
        if (it + 2 < 48) {
            int buf = (it + 2) % 3;
            tstage(As[buf], at + (size_t)(it + 2)*TILE, tid);
            tstage(Bs[buf], bt + (size_t)(it + 2)*TILE, tid);
            cp_commit();
        }
        gemm_stage_raw(As[it % 3], Bs[it % 3], warp_m, warp_n, r, c, acc);
    }
    #pragma unroll
    for (int j = 0; j < 4; j++) {
        int np0 = n0 + warp_n + j*8 + 2*c;
        float b0v = g_bfinal[np0], b1v = g_bfinal[np0 + 1];
        #pragma unroll
        for (int i = 0; i < 2; i++) {
            float4 d = acc[i][j];
            int R0 = m0 + warp_m + i*16 + r;
            *(float2*)&out[(size_t)R0*512 + np0] = make_float2(d.x + b0v, d.y + b1v);
            *(float2*)&out[(size_t)(R0 + 8)*512 + np0] = make_float2(d.z + b0v, d.w + b1v);
        }
    }
}

extern "C" void kernel_launch(void* const* d_in, const int* in_sizes, int n_in,
                              void* d_out, int out_size) {
    const float* Q    = (const float*)d_in[0];
    const float* K    = (const float*)d_in[1];
    const float* V    = (const float*)d_in[2];
    const unsigned char* mask = (const unsigned char*)d_in[3];
    const float* edge = (const float*)d_in[4];
    const float* W_Q  = (const float*)d_in[5];
    const float* b_Q  = (const float*)d_in[6];
    const float* W_K  = (const float*)d_in[7];
    const float* b_K  = (const float*)d_in[8];
    const float* W_V  = (const float*)d_in[9];
    const float* b_V  = (const float*)d_in[10];
    const float* W_Ke = (const float*)d_in[11];
    const float* b_Ke = (const float*)d_in[12];
    const float* W_eb = (const float*)d_in[13];
    const float* b_eb = (const float*)d_in[14];
    const float* W_eo = (const float*)d_in[15];
    const float* b_eo = (const float*)d_in[16];
    const float* W_o  = (const float*)d_in[17];
    const float* b_o  = (const float*)d_in[18];
    float* out = (float*)d_out;

    static cudaStream_t s1 = nullptr;
    static cudaEvent_t evF, evB, evS, evE;
    if (!s1) {
        cudaStreamCreateWithFlags(&s1, cudaStreamNonBlocking);
        cudaEventCreateWithFlags(&evF, cudaEventDisableTiming);
        cudaEventCreateWithFlags(&evB, cudaEventDisableTiming);
        cudaEventCreateWithFlags(&evS, cudaEventDisableTiming);
        cudaEventCreateWithFlags(&evE, cudaEventDisableTiming);
    }

    //   s1:   biask -> prep1 -> prep2 -> (wait evS) e
    //   main: proj -> (wait evB) scores -> ctx -> (wait evE) final
    cudaEventRecord(evF, 0);
    cudaStreamWaitEvent(s1, evF, 0);
    biask_kernel<<<2048, 256, 0, s1>>>(edge, mask, W_eb, b_eb);          // 1
    cudaEventRecord(evB, s1);
    proj_kernel<<<dim3(8, 32, 3), 128>>>(Q, K, V, W_Q, W_K, W_V, b_Q, b_K, b_V); // 2
    prep1_kernel<<<512, 256, 0, s1>>>(W_Ke, b_Ke, W_eo, b_eo);           // 3
    cudaStreamWaitEvent(0, evB, 0);
    scores_kernel<<<dim3(16, 32), 256>>>();                               // 4 (profiled)
    prep2_kernel<<<512, 64, 0, s1>>>(W_o, b_o);                           // 5
    cudaEventRecord(evS, 0);
    cudaStreamWaitEvent(s1, evS, 0);
    e_kernel<<<dim3(64, 4), 256, 0, s1>>>(edge);                          // 6
    ctx_kernel<<<dim3(8, 32), 128>>>();                                   // 7
    cudaEventRecord(evE, s1);
    cudaStreamWaitEvent(0, evE, 0);
    final_kernel<<<dim3(8, 32), 128>>>(out);                              // 8
}